// round 4
// baseline (speedup 1.0000x reference)
#include <cuda_runtime.h>
#include <cstdint>
#include <cstddef>

#define Lq 2048
#define Hh 16
#define Cc 64
#define Bb 2

// Output layout: [context (B,L,H*C)] [scores (B,H,L,L)] [weights (B,H,L,L)]
#define OFF_S  ((size_t)Bb * Lq * Hh * Cc)
#define NSCORE ((size_t)Bb * Hh * Lq * Lq)
#define OFF_W  (OFF_S + NSCORE)

#define PADA 68    // 64-col tiles pad
#define PADW 132   // 128-col W tile pad (float4-aligned rows)
#define PADV 133   // V-transpose pad (odd-ish stride -> ~2-way max)

// smem: pass1 = Qs[128*PADA] + Ks[128*PADA] = 17408 floats
//       pass2 = Ws[128*PADW] + Vt[64*PADV]  = 16896 + 8512 = 25408 floats
#define SMEM_FLOATS 25408
#define SMEM_BYTES  (SMEM_FLOATS * 4)

__device__ int g_mask_kind;  // 0 = u8/bool, 1 = int32, 2 = float32

// ---------------------------------------------------------------------------
__global__ void detect_mask_kernel(const void* __restrict__ m) {
    if (threadIdx.x == 0 && blockIdx.x == 0) {
        const unsigned int* w = (const unsigned int*)m;
        bool i32 = true, f32 = true;
        for (int t = 0; t < 256; t++) {
            unsigned int v = w[t];
            if (v > 1u) i32 = false;
            if (v != 0u && v != 0x3F800000u) f32 = false;
        }
        g_mask_kind = i32 ? 1 : (f32 ? 2 : 0);
    }
}

// ---------------------------------------------------------------------------
__device__ __forceinline__ float f2tf(float x) {
    unsigned r;
    asm("cvt.rna.tf32.f32 %0, %1;" : "=r"(r) : "f"(x));
    return __uint_as_float(r);
}

__device__ __forceinline__ void mma_tf32(float (&d)[4], const float (&a)[4],
                                         float b0, float b1) {
    asm volatile(
        "mma.sync.aligned.m16n8k8.row.col.f32.tf32.tf32.f32 "
        "{%0,%1,%2,%3}, {%4,%5,%6,%7}, {%8,%9}, {%0,%1,%2,%3};"
        : "+f"(d[0]), "+f"(d[1]), "+f"(d[2]), "+f"(d[3])
        : "r"(__float_as_uint(a[0])), "r"(__float_as_uint(a[1])),
          "r"(__float_as_uint(a[2])), "r"(__float_as_uint(a[3])),
          "r"(__float_as_uint(b0)), "r"(__float_as_uint(b1)));
}

__device__ __forceinline__ float2 mask2f(int kind, const void* mask, size_t off) {
    float2 r;
    if (kind == 1) {
        const int2 m = *(const int2*)((const int*)mask + off);
        r.x = m.x ? 1.f : 0.f; r.y = m.y ? 1.f : 0.f;
    } else if (kind == 2) {
        const float2 m = *(const float2*)((const float*)mask + off);
        r.x = (m.x != 0.f) ? 1.f : 0.f; r.y = (m.y != 0.f) ? 1.f : 0.f;
    } else {
        const uchar2 m = *(const uchar2*)((const unsigned char*)mask + off);
        r.x = m.x ? 1.f : 0.f; r.y = m.y ? 1.f : 0.f;
    }
    return r;
}

__device__ __forceinline__ float4 mask4f(int kind, const void* mask, size_t off) {
    float4 r;
    if (kind == 1) {
        const int4 m = *(const int4*)((const int*)mask + off);
        r.x = m.x ? 1.f : 0.f; r.y = m.y ? 1.f : 0.f;
        r.z = m.z ? 1.f : 0.f; r.w = m.w ? 1.f : 0.f;
    } else if (kind == 2) {
        const float4 m = *(const float4*)((const float*)mask + off);
        r.x = (m.x != 0.f) ? 1.f : 0.f; r.y = (m.y != 0.f) ? 1.f : 0.f;
        r.z = (m.z != 0.f) ? 1.f : 0.f; r.w = (m.w != 0.f) ? 1.f : 0.f;
    } else {
        const uchar4 m = *(const uchar4*)((const unsigned char*)mask + off);
        r.x = m.x ? 1.f : 0.f; r.y = m.y ? 1.f : 0.f;
        r.z = m.z ? 1.f : 0.f; r.w = m.w ? 1.f : 0.f;
    }
    return r;
}

// ---------------------------------------------------------------------------
// Fused attention: one CTA handles a 128-row strip of one (b,h).
// Pass 1: scores = QK^T + edge (write), rowsum(exp) accumulation.
// Pass 2: weights = exp*inv (write), ctx += W*V via TF32 mma.
// ---------------------------------------------------------------------------
__global__ __launch_bounds__(256, 2) void fused_attn_kernel(
    const float* __restrict__ q, const float* __restrict__ k,
    const float* __restrict__ v, const void* __restrict__ mask,
    const float* __restrict__ edge, float* __restrict__ out) {
    extern __shared__ float sm[];
    float* Qs = sm;                  // pass1: [128][PADA]
    float* Ks = sm + 128 * PADA;     // pass1: [128][PADA]
    float* Ws = sm;                  // pass2: [128][PADW]
    float* Vt = sm + 128 * PADW;     // pass2: [64][PADV]
    __shared__ float rowsum[128];
    __shared__ float invs[128];

    float* scores  = out + OFF_S;
    float* weights = out + OFF_W;

    const int bh = blockIdx.y;
    const int b = bh >> 4, h = bh & 15;
    const int i0 = blockIdx.x << 7;
    const int tid = threadIdx.x;
    const int warp = tid >> 5, lane = tid & 31;
    const int gid = lane >> 2, qid = lane & 3;
    const int kind = g_mask_kind;

    if (tid < 128) rowsum[tid] = 0.0f;

    // Load Q tile (128 x 64) -> Qs[i][c], tf32
#pragma unroll
    for (int r = 0; r < 8; r++) {
        const int idx = r * 256 + tid;
        const int row = idx >> 4;
        const int c4 = (idx & 15) * 4;
        const float4 vq = *(const float4*)(q +
            ((size_t)(b * Lq + i0 + row) * Hh + h) * Cc + c4);
        float* d = &Qs[row * PADA + c4];
        d[0] = f2tf(vq.x); d[1] = f2tf(vq.y);
        d[2] = f2tf(vq.z); d[3] = f2tf(vq.w);
    }

    // ------------------------- PASS 1 -------------------------
    {
        const int wi = warp >> 1, wj = warp & 1;
        const int ibase = wi * 32, jbase = wj * 64;

        for (int jt = 0; jt < 16; jt++) {
            const int j0 = jt << 7;
            __syncthreads();   // previous mma done (and Qs ready on jt=0)
            // load K tile (128 x 64) -> Ks[j][c]
#pragma unroll
            for (int r = 0; r < 8; r++) {
                const int idx = r * 256 + tid;
                const int row = idx >> 4;
                const int c4 = (idx & 15) * 4;
                const float4 vk = *(const float4*)(k +
                    ((size_t)(b * Lq + j0 + row) * Hh + h) * Cc + c4);
                float* d = &Ks[row * PADA + c4];
                d[0] = f2tf(vk.x); d[1] = f2tf(vk.y);
                d[2] = f2tf(vk.z); d[3] = f2tf(vk.w);
            }
            __syncthreads();

            float acc[2][8][4] = {};
#pragma unroll
            for (int kk = 0; kk < 8; kk++) {
                const int k0 = kk * 8;
                float a[2][4];
#pragma unroll
                for (int m = 0; m < 2; m++) {
                    const int rr = ibase + m * 16 + gid;
                    a[m][0] = Qs[rr * PADA + k0 + qid];
                    a[m][1] = Qs[(rr + 8) * PADA + k0 + qid];
                    a[m][2] = Qs[rr * PADA + k0 + qid + 4];
                    a[m][3] = Qs[(rr + 8) * PADA + k0 + qid + 4];
                }
#pragma unroll
                for (int n = 0; n < 8; n++) {
                    const int cc = jbase + n * 8 + gid;
                    const float b0 = Ks[cc * PADA + k0 + qid];
                    const float b1 = Ks[cc * PADA + k0 + qid + 4];
                    mma_tf32(acc[0][n], a[0], b0, b1);
                    mma_tf32(acc[1][n], a[1], b0, b1);
                }
            }

            // Epilogue: edge add, scores write, exp row-sum partials
            float rs[2][2] = {};
#pragma unroll
            for (int m = 0; m < 2; m++) {
#pragma unroll
                for (int n = 0; n < 8; n++) {
                    const int i = i0 + ibase + m * 16 + gid;
                    const int j = j0 + jbase + n * 8 + 2 * qid;
                    const size_t e0 = ((size_t)h * Lq + i) * Lq + j;
                    const size_t s0 = ((size_t)bh * Lq + i) * Lq + j;
                    const float2 ea = *(const float2*)(edge + e0);
                    const float2 eb = *(const float2*)(edge + e0 + 8 * (size_t)Lq);
                    float2 oa, ob;
                    oa.x = acc[m][n][0] + ea.x; oa.y = acc[m][n][1] + ea.y;
                    ob.x = acc[m][n][2] + eb.x; ob.y = acc[m][n][3] + eb.y;
                    *(float2*)(scores + s0) = oa;
                    *(float2*)(scores + s0 + 8 * (size_t)Lq) = ob;
                    const float2 ma = mask2f(kind, mask,
                        ((size_t)(b * Lq + i)) * Lq + j);
                    const float2 mb = mask2f(kind, mask,
                        ((size_t)(b * Lq + i + 8)) * Lq + j);
                    rs[m][0] += (ma.x != 0.f ? __expf(oa.x * 0.125f) : 0.f)
                              + (ma.y != 0.f ? __expf(oa.y * 0.125f) : 0.f);
                    rs[m][1] += (mb.x != 0.f ? __expf(ob.x * 0.125f) : 0.f)
                              + (mb.y != 0.f ? __expf(ob.y * 0.125f) : 0.f);
                }
            }
#pragma unroll
            for (int m = 0; m < 2; m++) {
#pragma unroll
                for (int hh = 0; hh < 2; hh++) {
                    float vsum = rs[m][hh];
                    vsum += __shfl_xor_sync(0xffffffffu, vsum, 1);
                    vsum += __shfl_xor_sync(0xffffffffu, vsum, 2);
                    if (qid == 0)
                        atomicAdd(&rowsum[ibase + m * 16 + gid + hh * 8], vsum);
                }
            }
        }
    }

    __syncthreads();
    if (tid < 128) {
        const float s = rowsum[tid];
        invs[tid] = (s != 0.0f) ? 1.0f / s : 0.0f;
    }

    // ------------------------- PASS 2 -------------------------
    {
        const int wi = warp >> 1, wc = warp & 1;
        const int ibase = wi * 32, cbase = wc * 32;
        float accc[2][4][4] = {};

        for (int jt = 0; jt < 16; jt++) {
            const int j0 = jt << 7;
            __syncthreads();   // prev mma done / invs ready on jt=0
            // Stage W tile: read scores (L2-hot), compute w, write weights,
            // stash tf32 w into Ws[i][j].
#pragma unroll
            for (int r = 0; r < 16; r++) {
                const int idx = r * 256 + tid;
                const int row = idx >> 5;           // local i
                const int c4 = (idx & 31) * 4;      // local j
                const size_t gs = ((size_t)bh * Lq + i0 + row) * Lq + j0 + c4;
                const float4 s4 = *(const float4*)(scores + gs);
                const float4 m4 = mask4f(kind, mask,
                    ((size_t)(b * Lq + i0 + row)) * Lq + j0 + c4);
                const float iv = invs[row];
                float4 w4;
                w4.x = (m4.x != 0.f) ? __expf(s4.x * 0.125f) * iv : 0.f;
                w4.y = (m4.y != 0.f) ? __expf(s4.y * 0.125f) * iv : 0.f;
                w4.z = (m4.z != 0.f) ? __expf(s4.z * 0.125f) * iv : 0.f;
                w4.w = (m4.w != 0.f) ? __expf(s4.w * 0.125f) * iv : 0.f;
                *(float4*)(weights + gs) = w4;
                float4 wt;
                wt.x = f2tf(w4.x); wt.y = f2tf(w4.y);
                wt.z = f2tf(w4.z); wt.w = f2tf(w4.w);
                *(float4*)&Ws[row * PADW + c4] = wt;
            }
            // Stage V tile transposed: Vt[c][j]
#pragma unroll
            for (int r = 0; r < 8; r++) {
                const int idx = r * 256 + tid;
                const int jr = idx >> 4;
                const int c4 = (idx & 15) * 4;
                const float4 vv = *(const float4*)(v +
                    ((size_t)(b * Lq + j0 + jr) * Hh + h) * Cc + c4);
                Vt[(c4 + 0) * PADV + jr] = f2tf(vv.x);
                Vt[(c4 + 1) * PADV + jr] = f2tf(vv.y);
                Vt[(c4 + 2) * PADV + jr] = f2tf(vv.z);
                Vt[(c4 + 3) * PADV + jr] = f2tf(vv.w);
            }
            __syncthreads();

#pragma unroll
            for (int kk = 0; kk < 16; kk++) {
                const int k0 = kk * 8;
                float a[2][4];
#pragma unroll
                for (int m = 0; m < 2; m++) {
                    const int rr = ibase + m * 16 + gid;
                    a[m][0] = Ws[rr * PADW + k0 + qid];
                    a[m][1] = Ws[(rr + 8) * PADW + k0 + qid];
                    a[m][2] = Ws[rr * PADW + k0 + qid + 4];
                    a[m][3] = Ws[(rr + 8) * PADW + k0 + qid + 4];
                }
#pragma unroll
                for (int n = 0; n < 4; n++) {
                    const int cc = cbase + n * 8 + gid;
                    const float b0 = Vt[cc * PADV + k0 + qid];
                    const float b1 = Vt[cc * PADV + k0 + qid + 4];
                    mma_tf32(accc[0][n], a[0], b0, b1);
                    mma_tf32(accc[1][n], a[1], b0, b1);
                }
            }
        }

        // ctx epilogue
#pragma unroll
        for (int m = 0; m < 2; m++) {
#pragma unroll
            for (int n = 0; n < 4; n++) {
                const int i = i0 + ibase + m * 16 + gid;
                const int c = h * Cc + cbase + n * 8 + 2 * qid;
                float2 oa, ob;
                oa.x = accc[m][n][0]; oa.y = accc[m][n][1];
                ob.x = accc[m][n][2]; ob.y = accc[m][n][3];
                *(float2*)(out + ((size_t)(b * Lq + i)) * (Hh * Cc) + c) = oa;
                *(float2*)(out + ((size_t)(b * Lq + i + 8)) * (Hh * Cc) + c) = ob;
            }
        }
    }
}

// ---------------------------------------------------------------------------
extern "C" void kernel_launch(void* const* d_in, const int* in_sizes, int n_in,
                              void* d_out, int out_size) {
    (void)in_sizes; (void)n_in; (void)out_size;
    const float* q    = (const float*)d_in[0];
    const float* k    = (const float*)d_in[1];
    const float* v    = (const float*)d_in[2];
    const void*  mask = d_in[3];
    const float* edge = (const float*)d_in[4];
    float* out = (float*)d_out;

    cudaFuncSetAttribute(fused_attn_kernel,
        cudaFuncAttributeMaxDynamicSharedMemorySize, SMEM_BYTES);

    detect_mask_kernel<<<1, 32>>>(mask);

    dim3 grid(Lq / 128, Bb * Hh);
    fused_attn_kernel<<<grid, 256, SMEM_BYTES>>>(q, k, v, mask, edge, out);
}

// round 5
// speedup vs baseline: 1.4236x; 1.4236x over previous
#include <cuda_runtime.h>
#include <cstdint>
#include <cstddef>

#define Lq 2048
#define Hh 16
#define Cc 64
#define Bb 2

// Output layout: [context (B,L,H*C)] [scores (B,H,L,L)] [weights (B,H,L,L)]
#define OFF_S  ((size_t)Bb * Lq * Hh * Cc)
#define NSCORE ((size_t)Bb * Hh * Lq * Lq)
#define OFF_W  (OFF_S + NSCORE)

#define PADA 68
#define PADV 133

#define SMEM_SCORES ((64 * PADA + 128 * PADA) * 4)   // Qs + Ks = 52224 B
#define SMEM_AV     ((64 * PADA + 64 * PADV) * 4)    // Ws + Vt = 51456 B

__device__ int g_mask_kind;  // 0 = u8/bool, 1 = int32, 2 = float32

// ---------------------------------------------------------------------------
__global__ void detect_mask_kernel(const void* __restrict__ m) {
    if (threadIdx.x == 0 && blockIdx.x == 0) {
        const unsigned int* w = (const unsigned int*)m;
        bool i32 = true, f32 = true;
        for (int t = 0; t < 256; t++) {
            unsigned int v = w[t];
            if (v > 1u) i32 = false;
            if (v != 0u && v != 0x3F800000u) f32 = false;
        }
        g_mask_kind = i32 ? 1 : (f32 ? 2 : 0);
    }
}

// ---------------------------------------------------------------------------
__device__ __forceinline__ float f2tf(float x) {
    unsigned r;
    asm("cvt.rna.tf32.f32 %0, %1;" : "=r"(r) : "f"(x));
    return __uint_as_float(r);
}

__device__ __forceinline__ void mma_tf32(float (&d)[4], const float (&a)[4],
                                         float b0, float b1) {
    asm volatile(
        "mma.sync.aligned.m16n8k8.row.col.f32.tf32.tf32.f32 "
        "{%0,%1,%2,%3}, {%4,%5,%6,%7}, {%8,%9}, {%0,%1,%2,%3};"
        : "+f"(d[0]), "+f"(d[1]), "+f"(d[2]), "+f"(d[3])
        : "r"(__float_as_uint(a[0])), "r"(__float_as_uint(a[1])),
          "r"(__float_as_uint(a[2])), "r"(__float_as_uint(a[3])),
          "r"(__float_as_uint(b0)), "r"(__float_as_uint(b1)));
}

// ---------------------------------------------------------------------------
// Kernel 1: scores = QK^T + edge. CTA tile 64(i) x 128(j), K=64 one pass.
// 8 warps as 4(i) x 2(j): warp = 16i x 64j.
// ---------------------------------------------------------------------------
__global__ __launch_bounds__(256, 3) void scores_kernel(
    const float* __restrict__ q, const float* __restrict__ k,
    const float* __restrict__ edge, float* __restrict__ out_scores) {
    extern __shared__ float sm[];
    float* Qs = sm;                 // [64][PADA]  : [i][c]
    float* Ks = sm + 64 * PADA;     // [128][PADA] : [j][c]

    const int bh = blockIdx.z;
    const int b = bh >> 4, h = bh & 15;
    const int i0 = blockIdx.y << 6;
    const int j0 = blockIdx.x << 7;
    const int tid = threadIdx.x;

#pragma unroll
    for (int r = 0; r < 4; r++) {
        const int idx = r * 256 + tid;
        const int row = idx >> 4;
        const int c4 = (idx & 15) * 4;
        const float4 vq = *(const float4*)(q +
            ((size_t)(b * Lq + i0 + row) * Hh + h) * Cc + c4);
        float* d = &Qs[row * PADA + c4];
        d[0] = f2tf(vq.x); d[1] = f2tf(vq.y);
        d[2] = f2tf(vq.z); d[3] = f2tf(vq.w);
    }
#pragma unroll
    for (int r = 0; r < 8; r++) {
        const int idx = r * 256 + tid;
        const int row = idx >> 4;
        const int c4 = (idx & 15) * 4;
        const float4 vk = *(const float4*)(k +
            ((size_t)(b * Lq + j0 + row) * Hh + h) * Cc + c4);
        float* d = &Ks[row * PADA + c4];
        d[0] = f2tf(vk.x); d[1] = f2tf(vk.y);
        d[2] = f2tf(vk.z); d[3] = f2tf(vk.w);
    }
    __syncthreads();

    const int warp = tid >> 5, lane = tid & 31;
    const int wi = warp >> 1, wj = warp & 1;
    const int ibase = wi * 16, jbase = wj * 64;
    const int gid = lane >> 2, qid = lane & 3;

    float acc[8][4] = {};

#pragma unroll
    for (int kk = 0; kk < 8; kk++) {
        const int k0 = kk * 8;
        float a[4];
        const int rr = ibase + gid;
        a[0] = Qs[rr * PADA + k0 + qid];
        a[1] = Qs[(rr + 8) * PADA + k0 + qid];
        a[2] = Qs[rr * PADA + k0 + qid + 4];
        a[3] = Qs[(rr + 8) * PADA + k0 + qid + 4];
#pragma unroll
        for (int n = 0; n < 8; n++) {
            const int cc = jbase + n * 8 + gid;
            const float b0 = Ks[cc * PADA + k0 + qid];
            const float b1 = Ks[cc * PADA + k0 + qid + 4];
            mma_tf32(acc[n], a, b0, b1);
        }
    }

#pragma unroll
    for (int n = 0; n < 8; n++) {
        const int i = i0 + ibase + gid;
        const int j = j0 + jbase + n * 8 + 2 * qid;
        const size_t e0 = ((size_t)h * Lq + i) * Lq + j;
        const size_t s0 = ((size_t)bh * Lq + i) * Lq + j;
        const float2 ea = *(const float2*)(edge + e0);
        const float2 eb = *(const float2*)(edge + e0 + 8 * (size_t)Lq);
        float2 oa, ob;
        oa.x = acc[n][0] + ea.x; oa.y = acc[n][1] + ea.y;
        ob.x = acc[n][2] + eb.x; ob.y = acc[n][3] + eb.y;
        *(float2*)(out_scores + s0) = oa;
        *(float2*)(out_scores + s0 + 8 * (size_t)Lq) = ob;
    }
}

// ---------------------------------------------------------------------------
// Kernel 2: masked softmax. One 256-thread block per (b,h,i) row.
// ---------------------------------------------------------------------------
__global__ __launch_bounds__(256) void softmax_kernel(
    const float* __restrict__ scores, const void* __restrict__ mask,
    float* __restrict__ wout) {
    const int row = blockIdx.x;
    const int bh = row >> 11;
    const int i  = row & (Lq - 1);
    const int b  = bh >> 4;
    const size_t soff = (size_t)row * Lq;
    const size_t moff = ((size_t)(b * Lq + i)) * Lq;
    const int tid = threadIdx.x;
    const int kind = g_mask_kind;

    const float4* sp = (const float4*)(scores + soff);
    const float4 s0 = sp[tid];
    const float4 s1 = sp[256 + tid];

    float mb[8];
    if (kind == 1) {
        const int4* mp = (const int4*)((const int*)mask + moff);
        const int4 m0 = mp[tid], m1 = mp[256 + tid];
        mb[0] = m0.x ? 1.f : 0.f; mb[1] = m0.y ? 1.f : 0.f;
        mb[2] = m0.z ? 1.f : 0.f; mb[3] = m0.w ? 1.f : 0.f;
        mb[4] = m1.x ? 1.f : 0.f; mb[5] = m1.y ? 1.f : 0.f;
        mb[6] = m1.z ? 1.f : 0.f; mb[7] = m1.w ? 1.f : 0.f;
    } else if (kind == 2) {
        const float4* mp = (const float4*)((const float*)mask + moff);
        const float4 m0 = mp[tid], m1 = mp[256 + tid];
        mb[0] = (m0.x != 0.f); mb[1] = (m0.y != 0.f);
        mb[2] = (m0.z != 0.f); mb[3] = (m0.w != 0.f);
        mb[4] = (m1.x != 0.f); mb[5] = (m1.y != 0.f);
        mb[6] = (m1.z != 0.f); mb[7] = (m1.w != 0.f);
    } else {
        const uchar4* mp = (const uchar4*)((const unsigned char*)mask + moff);
        const uchar4 m0 = mp[tid], m1 = mp[256 + tid];
        mb[0] = m0.x ? 1.f : 0.f; mb[1] = m0.y ? 1.f : 0.f;
        mb[2] = m0.z ? 1.f : 0.f; mb[3] = m0.w ? 1.f : 0.f;
        mb[4] = m1.x ? 1.f : 0.f; mb[5] = m1.y ? 1.f : 0.f;
        mb[6] = m1.z ? 1.f : 0.f; mb[7] = m1.w ? 1.f : 0.f;
    }

    const float sv[8] = {s0.x, s0.y, s0.z, s0.w, s1.x, s1.y, s1.z, s1.w};
    float x[8];
#pragma unroll
    for (int t = 0; t < 8; t++)
        x[t] = (mb[t] != 0.f) ? sv[t] * 0.125f : -1e18f;

    float mx = x[0];
#pragma unroll
    for (int t = 1; t < 8; t++) mx = fmaxf(mx, x[t]);
#pragma unroll
    for (int o = 16; o; o >>= 1) mx = fmaxf(mx, __shfl_xor_sync(0xffffffffu, mx, o));

    __shared__ float red_max[8];
    __shared__ float red_sum[8];
    if ((tid & 31) == 0) red_max[tid >> 5] = mx;
    __syncthreads();
    mx = red_max[0];
#pragma unroll
    for (int wi = 1; wi < 8; wi++) mx = fmaxf(mx, red_max[wi]);

    float e[8];
    float s = 0.0f;
#pragma unroll
    for (int t = 0; t < 8; t++) {
        e[t] = __expf(x[t] - mx);
        s += e[t];
    }
#pragma unroll
    for (int o = 16; o; o >>= 1) s += __shfl_xor_sync(0xffffffffu, s, o);
    if ((tid & 31) == 0) red_sum[tid >> 5] = s;
    __syncthreads();
    s = red_sum[0];
#pragma unroll
    for (int wi = 1; wi < 8; wi++) s += red_sum[wi];

    const float inv = 1.0f / s;
    float4 w0, w1;
    w0.x = e[0] * inv * mb[0]; w0.y = e[1] * inv * mb[1];
    w0.z = e[2] * inv * mb[2]; w0.w = e[3] * inv * mb[3];
    w1.x = e[4] * inv * mb[4]; w1.y = e[5] * inv * mb[5];
    w1.z = e[6] * inv * mb[6]; w1.w = e[7] * inv * mb[7];
    float4* wp = (float4*)(wout + soff);
    wp[tid] = w0;
    wp[256 + tid] = w1;
}

// ---------------------------------------------------------------------------
// Kernel 3: ctx = W * V. CTA tile 64(i) x 64(c), j chunks of 64.
// 8 warps as 4(i) x 2(c): warp = 16i x 32c.
// ---------------------------------------------------------------------------
__global__ __launch_bounds__(256, 4) void av_kernel(
    const float* __restrict__ w, const float* __restrict__ v,
    float* __restrict__ ctx) {
    extern __shared__ float sm[];
    float* Ws = sm;                // [64][PADA] : [i][j]
    float* Vt = sm + 64 * PADA;    // [64][PADV] : [c][j]

    const int bh = blockIdx.y;
    const int b = bh >> 4, h = bh & 15;
    const int i0 = blockIdx.x << 6;
    const int tid = threadIdx.x;
    const int warp = tid >> 5, lane = tid & 31;
    const int wi = warp >> 1, wc = warp & 1;
    const int ibase = wi * 16, cbase = wc * 32;
    const int gid = lane >> 2, qid = lane & 3;

    float acc[4][4] = {};

    for (int j0 = 0; j0 < Lq; j0 += 64) {
        __syncthreads();
#pragma unroll
        for (int r = 0; r < 4; r++) {
            const int idx = r * 256 + tid;
            const int row = idx >> 4;
            const int j4 = (idx & 15) * 4;
            const float4 vw = *(const float4*)(w +
                ((size_t)bh * Lq + i0 + row) * Lq + j0 + j4);
            float* d = &Ws[row * PADA + j4];
            d[0] = f2tf(vw.x); d[1] = f2tf(vw.y);
            d[2] = f2tf(vw.z); d[3] = f2tf(vw.w);
        }
#pragma unroll
        for (int r = 0; r < 4; r++) {
            const int idx = r * 256 + tid;
            const int jr = idx >> 4;
            const int c4 = (idx & 15) * 4;
            const float4 vv = *(const float4*)(v +
                ((size_t)(b * Lq + j0 + jr) * Hh + h) * Cc + c4);
            Vt[(c4 + 0) * PADV + jr] = f2tf(vv.x);
            Vt[(c4 + 1) * PADV + jr] = f2tf(vv.y);
            Vt[(c4 + 2) * PADV + jr] = f2tf(vv.z);
            Vt[(c4 + 3) * PADV + jr] = f2tf(vv.w);
        }
        __syncthreads();

#pragma unroll
        for (int kk = 0; kk < 8; kk++) {
            const int k0 = kk * 8;
            float a[4];
            const int rr = ibase + gid;
            a[0] = Ws[rr * PADA + k0 + qid];
            a[1] = Ws[(rr + 8) * PADA + k0 + qid];
            a[2] = Ws[rr * PADA + k0 + qid + 4];
            a[3] = Ws[(rr + 8) * PADA + k0 + qid + 4];
#pragma unroll
            for (int n = 0; n < 4; n++) {
                const int cc = cbase + n * 8 + gid;
                const float b0 = Vt[cc * PADV + k0 + qid];
                const float b1 = Vt[cc * PADV + k0 + qid + 4];
                mma_tf32(acc[n], a, b0, b1);
            }
        }
    }

#pragma unroll
    for (int n = 0; n < 4; n++) {
        const int i = i0 + ibase + gid;
        const int c = h * Cc + cbase + n * 8 + 2 * qid;
        float2 oa, ob;
        oa.x = acc[n][0]; oa.y = acc[n][1];
        ob.x = acc[n][2]; ob.y = acc[n][3];
        *(float2*)(ctx + ((size_t)(b * Lq + i)) * (Hh * Cc) + c) = oa;
        *(float2*)(ctx + ((size_t)(b * Lq + i + 8)) * (Hh * Cc) + c) = ob;
    }
}

// ---------------------------------------------------------------------------
extern "C" void kernel_launch(void* const* d_in, const int* in_sizes, int n_in,
                              void* d_out, int out_size) {
    (void)in_sizes; (void)n_in; (void)out_size;
    const float* q    = (const float*)d_in[0];
    const float* k    = (const float*)d_in[1];
    const float* v    = (const float*)d_in[2];
    const void*  mask = d_in[3];
    const float* edge = (const float*)d_in[4];

    float* out     = (float*)d_out;
    float* ctx     = out;
    float* scores  = out + OFF_S;
    float* weights = out + OFF_W;

    cudaFuncSetAttribute(scores_kernel,
        cudaFuncAttributeMaxDynamicSharedMemorySize, SMEM_SCORES);
    cudaFuncSetAttribute(av_kernel,
        cudaFuncAttributeMaxDynamicSharedMemorySize, SMEM_AV);

    detect_mask_kernel<<<1, 32>>>(mask);

    {
        dim3 grid(Lq / 128, Lq / 64, Bb * Hh);
        scores_kernel<<<grid, 256, SMEM_SCORES>>>(q, k, edge, scores);
    }
    {
        softmax_kernel<<<Bb * Hh * Lq, 256>>>(scores, mask, weights);
    }
    {
        dim3 grid(Lq / 64, Bb * Hh);
        av_kernel<<<grid, 256, SMEM_AV>>>(weights, v, ctx);
    }
}